// round 1
// baseline (speedup 1.0000x reference)
#include <cuda_runtime.h>
#include <cstdint>

// TemporalCompressor: per-batch centered-window linear interpolation resample.
// encoded: [B, D, T] f32, ratio: [B] f32, out: [B, D, To] f32
// L = min(floor(To * r), T); start = (T - L)/2
// x = (i+0.5)*L/To - 0.5, clamped to [0, L-1]; linear interp between floor/ceil.

static constexpr int B_  = 32;
static constexpr int D_  = 512;
static constexpr int T_  = 8192;
static constexpr int TO_ = 4096;

__global__ __launch_bounds__(256, 8)
void temporal_compressor_kernel(const float* __restrict__ encoded,
                                const float* __restrict__ ratio,
                                float* __restrict__ out)
{
    const int d = blockIdx.y;
    const int b = blockIdx.z;

    // Per-batch window parameters (uniform across block for fixed b)
    const float r = __ldg(&ratio[b]);
    // floor in fp32 exactly as the reference computes it
    float Lf = floorf((float)TO_ * r);
    int   L  = (int)Lf;
    if (L > T_) { L = T_; Lf = (float)T_; }
    const int   start = (T_ - L) >> 1;
    const float scale = Lf * (1.0f / (float)TO_);
    const float Lm1f  = (float)(L - 1);
    const int   Lm1   = L - 1;

    const float* __restrict__ src = encoded + ((size_t)b * D_ + d) * T_ + start;
    float* __restrict__ dst       = out     + ((size_t)b * D_ + d) * TO_;

    const int i0 = (blockIdx.x * blockDim.x + threadIdx.x) * 4;
    if (i0 >= TO_) return;

    float res[4];
#pragma unroll
    for (int k = 0; k < 4; ++k) {
        const int i = i0 + k;
        float x = fmaf((float)i + 0.5f, scale, -0.5f);
        x = fminf(fmaxf(x, 0.0f), Lm1f);
        const int   lo = (int)x;                 // x >= 0, so trunc == floor
        const int   hi = min(lo + 1, Lm1);
        const float w  = x - (float)lo;
        const float g_lo = __ldg(&src[lo]);
        const float g_hi = __ldg(&src[hi]);
        res[k] = fmaf(g_hi - g_lo, w, g_lo);     // g_lo*(1-w) + g_hi*w
    }

    // i0 is a multiple of 4 and dst row base is 16B-aligned -> STG.128 is safe
    *reinterpret_cast<float4*>(dst + i0) = make_float4(res[0], res[1], res[2], res[3]);
}

extern "C" void kernel_launch(void* const* d_in, const int* in_sizes, int n_in,
                              void* d_out, int out_size)
{
    const float* encoded = (const float*)d_in[0];
    const float* ratio   = (const float*)d_in[1];
    float* out           = (float*)d_out;

    dim3 block(256, 1, 1);
    dim3 grid(TO_ / (256 * 4), D_, B_);   // (4, 512, 32)
    temporal_compressor_kernel<<<grid, block>>>(encoded, ratio, out);
}

// round 2
// speedup vs baseline: 1.0358x; 1.0358x over previous
#include <cuda_runtime.h>
#include <cstdint>

// TemporalCompressor: per-batch centered-window linear interpolation resample.
// encoded: [B, D, T] f32, ratio: [B] f32, out: [B, D, To] f32
// L = min(floor(To * r), T); start = (T - L)/2
// x = (i+0.5)*L/To - 0.5, clamped to [0, L-1]; linear interp between floor/ceil.
//
// Mapping: one block per (b, d) row; warp lanes own CONSECUTIVE output indices
// so gather loads per warp span only 32*r floats (128-256 B -> 1-2 L1 lines per
// LDG) and stores are coalesced 128 B per warp-store. 16 independent iterations
// per thread, fully unrolled for MLP.

static constexpr int B_  = 32;
static constexpr int D_  = 512;
static constexpr int T_  = 8192;
static constexpr int TO_ = 4096;
static constexpr int NT  = 256;          // threads per block
static constexpr int IT  = TO_ / NT;     // 16 outputs per thread

__global__ __launch_bounds__(NT, 8)
void temporal_compressor_kernel(const float* __restrict__ encoded,
                                const float* __restrict__ ratio,
                                float* __restrict__ out)
{
    const int d = blockIdx.x;
    const int b = blockIdx.y;

    // Per-batch window parameters (uniform across block)
    const float r = __ldg(&ratio[b]);
    float Lf = floorf((float)TO_ * r);     // fp32 floor, exactly like reference
    int   L  = (int)Lf;
    if (L > T_) { L = T_; Lf = (float)T_; }
    const int   start = (T_ - L) >> 1;
    const float scale = Lf * (1.0f / (float)TO_);
    const float Lm1f  = (float)(L - 1);
    const int   Lm1   = L - 1;

    const float* __restrict__ src = encoded + ((size_t)b * D_ + d) * T_ + start;
    float* __restrict__ dst       = out     + ((size_t)b * D_ + d) * TO_;

    const int tid = threadIdx.x;

#pragma unroll
    for (int j = 0; j < IT; ++j) {
        const int i = tid + j * NT;
        float x = fmaf((float)i + 0.5f, scale, -0.5f);
        x = fminf(fmaxf(x, 0.0f), Lm1f);
        const int   lo = (int)x;                 // x >= 0 -> trunc == floor
        const int   hi = min(lo + 1, Lm1);
        const float w  = x - (float)lo;
        const float g_lo = __ldg(&src[lo]);
        const float g_hi = __ldg(&src[hi]);
        dst[i] = fmaf(g_hi - g_lo, w, g_lo);     // g_lo*(1-w) + g_hi*w
    }
}

extern "C" void kernel_launch(void* const* d_in, const int* in_sizes, int n_in,
                              void* d_out, int out_size)
{
    const float* encoded = (const float*)d_in[0];
    const float* ratio   = (const float*)d_in[1];
    float* out           = (float*)d_out;

    dim3 block(NT, 1, 1);
    dim3 grid(D_, B_, 1);   // one block per (b, d) row
    temporal_compressor_kernel<<<grid, block>>>(encoded, ratio, out);
}

// round 3
// speedup vs baseline: 1.0833x; 1.0459x over previous
#include <cuda_runtime.h>
#include <cstdint>

// TemporalCompressor: per-batch centered-window linear interpolation resample.
// encoded: [B, D, T] f32, ratio: [B] f32, out: [B, D, To] f32
//
// Strategy: one block per (b, d) row. Stage the row's source window into SMEM
// with cp.async 16B chunks (perfectly sequential, coalesced 128B/warp reads),
// then interpolate out of SMEM and write streaming stores.

static constexpr int B_  = 32;
static constexpr int D_  = 512;
static constexpr int T_  = 8192;
static constexpr int TO_ = 4096;
static constexpr int NT  = 256;          // threads per block
static constexpr int IT  = TO_ / NT;     // 16 outputs per thread

__global__ __launch_bounds__(NT, 6)
void temporal_compressor_kernel(const float* __restrict__ encoded,
                                const float* __restrict__ ratio,
                                float* __restrict__ out)
{
    __shared__ float buf[T_ + 8];        // up to full row + pad (32.8 KB)

    const int d = blockIdx.x;
    const int b = blockIdx.y;

    // Per-batch window parameters (uniform across block)
    const float r = __ldg(&ratio[b]);
    float Lf = floorf((float)TO_ * r);     // fp32 floor, exactly like reference
    int   L  = (int)Lf;
    if (L > T_) { L = T_; Lf = (float)T_; }
    const int   start = (T_ - L) >> 1;
    const float scale = Lf * (1.0f / (float)TO_);
    const float Lm1f  = (float)(L - 1);
    const int   Lm1   = L - 1;

    // 16B-aligned staging window: [aligned, aligned + len) covers [start, start+L)
    const int aligned = start & ~3;
    const int off     = start - aligned;                   // 0..3
    int len = ((off + L + 3) >> 2) << 2;                   // round up to 4 floats
    if (aligned + len > T_) len = T_ - aligned;            // clamp to row (still %4)

    const float* __restrict__ grow = encoded + ((size_t)b * D_ + d) * T_ + aligned;
    float* __restrict__ dst        = out     + ((size_t)b * D_ + d) * TO_;

    const int tid = threadIdx.x;

    // ---- Stage window into SMEM via cp.async (LDGSTS.128) ----
    {
        const int nchunks = len >> 2;                      // 16B chunks (<= 2048)
        uint32_t sbase = (uint32_t)__cvta_generic_to_shared(buf);
        for (int c = tid; c < nchunks; c += NT) {
            uint32_t saddr = sbase + c * 16u;
            const float* gaddr = grow + c * 4;
            asm volatile("cp.async.cg.shared.global [%0], [%1], 16;\n"
                         :: "r"(saddr), "l"(gaddr));
        }
        asm volatile("cp.async.commit_group;\n" ::: "memory");
        asm volatile("cp.async.wait_group 0;\n" ::: "memory");
    }
    __syncthreads();

    const float* __restrict__ src = buf + off;             // window base in SMEM

    // ---- Interpolate from SMEM, streaming stores ----
#pragma unroll
    for (int j = 0; j < IT; ++j) {
        const int i = tid + j * NT;
        float x = fmaf((float)i + 0.5f, scale, -0.5f);
        x = fminf(fmaxf(x, 0.0f), Lm1f);
        const int   lo = (int)x;                 // x >= 0 -> trunc == floor
        const int   hi = min(lo + 1, Lm1);
        const float w  = x - (float)lo;
        const float g_lo = src[lo];
        const float g_hi = src[hi];
        __stcs(dst + i, fmaf(g_hi - g_lo, w, g_lo));   // g_lo*(1-w) + g_hi*w
    }
}

extern "C" void kernel_launch(void* const* d_in, const int* in_sizes, int n_in,
                              void* d_out, int out_size)
{
    const float* encoded = (const float*)d_in[0];
    const float* ratio   = (const float*)d_in[1];
    float* out           = (float*)d_out;

    dim3 block(NT, 1, 1);
    dim3 grid(D_, B_, 1);   // one block per (b, d) row
    temporal_compressor_kernel<<<grid, block>>>(encoded, ratio, out);
}

// round 5
// speedup vs baseline: 1.0886x; 1.0049x over previous
#include <cuda_runtime.h>
#include <cstdint>

// TemporalCompressor: per-batch centered-window linear interpolation resample.
// encoded: [B, D, T] f32, ratio: [B] f32, out: [B, D, To] f32
//
// Strategy: 2 blocks per (b, d) row, each owning 2048 consecutive outputs.
// Each block cp.async-stages only its needed source sub-window (<=16.4 KB)
// into SMEM with sequential 16B chunks, then interpolates out of SMEM and
// writes streaming stores. 8 blocks/SM (full occupancy).

static constexpr int B_   = 32;
static constexpr int D_   = 512;
static constexpr int T_   = 8192;
static constexpr int TO_  = 4096;
static constexpr int NT   = 256;           // threads per block
static constexpr int NC   = 2;             // chunks per row
static constexpr int C_   = TO_ / NC;      // 2048 outputs per block
static constexpr int IT   = C_ / NT;       // 8 outputs per thread
static constexpr int SBUF = C_ * 2 + 8;    // max window floats (4098) + align pad

__global__ __launch_bounds__(NT, 8)
void temporal_compressor_kernel(const float* __restrict__ encoded,
                                const float* __restrict__ ratio,
                                float* __restrict__ out)
{
    __shared__ float buf[SBUF];            // 16.4 KB

    const int chunk = blockIdx.x;          // 0..NC-1
    const int d     = blockIdx.y;
    const int b     = blockIdx.z;

    // Per-batch window parameters (uniform across block)
    const float r = __ldg(&ratio[b]);
    float Lf = floorf((float)TO_ * r);     // fp32 floor, exactly like reference
    int   L  = (int)Lf;
    if (L > T_) { L = T_; Lf = (float)T_; }
    const int   start = (T_ - L) >> 1;
    const float scale = Lf * (1.0f / (float)TO_);
    const float Lm1f  = (float)(L - 1);
    const int   Lm1   = L - 1;

    const int i0 = chunk * C_;

    // Source sub-window [g0, g1] (window-relative) needed by outputs
    // [i0, i0+C_), computed with the SAME clamped expression as the interp
    // loop (x is monotonic in i, so endpoints bound everything between).
    float x0 = fmaf((float)i0 + 0.5f, scale, -0.5f);
    x0 = fminf(fmaxf(x0, 0.0f), Lm1f);
    const int g0 = (int)x0;
    float x1 = fmaf((float)(i0 + C_ - 1) + 0.5f, scale, -0.5f);
    x1 = fminf(fmaxf(x1, 0.0f), Lm1f);
    const int g1 = min((int)x1 + 1, Lm1);

    // Absolute row offset of window start; align DOWN to 16B within the row.
    // The row base (multiple of T_=8192 floats) is 16B-aligned, so
    // row + aligned_g is 16B-aligned for cp.async.
    const int s0        = start + g0;
    const int aligned_g = s0 & ~3;
    const int off       = s0 - aligned_g;              // 0..3
    int len = ((off + (g1 - g0 + 1) + 3) >> 2) << 2;   // round up to 4 floats
    if (aligned_g + len > T_) len = T_ - aligned_g;    // row clamp (keeps %4)

    const float* __restrict__ grow = encoded + ((size_t)b * D_ + d) * T_ + aligned_g;
    float* __restrict__ dst        = out     + ((size_t)b * D_ + d) * TO_;

    const int tid = threadIdx.x;

    // ---- Stage sub-window into SMEM via cp.async (LDGSTS.128) ----
    {
        const int nchunks = len >> 2;                  // 16B chunks (<= 1026)
        uint32_t sbase = (uint32_t)__cvta_generic_to_shared(buf);
        for (int c = tid; c < nchunks; c += NT) {
            uint32_t saddr = sbase + c * 16u;
            const float* gaddr = grow + c * 4;
            asm volatile("cp.async.cg.shared.global [%0], [%1], 16;\n"
                         :: "r"(saddr), "l"(gaddr));
        }
        asm volatile("cp.async.commit_group;\n" ::: "memory");
        asm volatile("cp.async.wait_group 0;\n" ::: "memory");
    }
    __syncthreads();

    // buf[k] = row[aligned_g + k] = window[aligned_g - start + k]
    // -> window[idx] = buf[idx - g0 + off]
    const int base = off - g0;

    // ---- Interpolate from SMEM, streaming stores ----
#pragma unroll
    for (int j = 0; j < IT; ++j) {
        const int i = i0 + tid + j * NT;
        float x = fmaf((float)i + 0.5f, scale, -0.5f);
        x = fminf(fmaxf(x, 0.0f), Lm1f);
        const int   lo = (int)x;                 // x >= 0 -> trunc == floor
        const int   hi = min(lo + 1, Lm1);
        const float w  = x - (float)lo;
        const float g_lo = buf[base + lo];
        const float g_hi = buf[base + hi];
        __stcs(dst + i, fmaf(g_hi - g_lo, w, g_lo));   // g_lo*(1-w) + g_hi*w
    }
}

extern "C" void kernel_launch(void* const* d_in, const int* in_sizes, int n_in,
                              void* d_out, int out_size)
{
    const float* encoded = (const float*)d_in[0];
    const float* ratio   = (const float*)d_in[1];
    float* out           = (float*)d_out;

    dim3 block(NT, 1, 1);
    dim3 grid(NC, D_, B_);   // (2, 512, 32) = 32768 blocks
    temporal_compressor_kernel<<<grid, block>>>(encoded, ratio, out);
}

// round 6
// speedup vs baseline: 1.1067x; 1.0166x over previous
#include <cuda_runtime.h>
#include <cstdint>

// TemporalCompressor: per-batch centered-window linear interpolation resample.
// encoded: [B, D, T] f32, ratio: [B] f32, out: [B, D, To] f32
//
// Strategy: 2 blocks per (b, d) row, each owning 2048 consecutive outputs.
// The needed source sub-window (<=16.4 KB) is staged into SMEM with ONE
// cp.async.bulk (TMA bulk engine) + mbarrier, then threads interpolate from
// SMEM and write float4 streaming stores.

static constexpr int B_   = 32;
static constexpr int D_   = 512;
static constexpr int T_   = 8192;
static constexpr int TO_  = 4096;
static constexpr int NT   = 256;           // threads per block
static constexpr int NC   = 2;             // chunks per row
static constexpr int C_   = TO_ / NC;      // 2048 outputs per block
static constexpr int V4   = C_ / (NT * 4); // 2 float4 groups per thread
static constexpr int SBUF = C_ * 2 + 8;    // max window floats (4104 needed) + pad

__global__ __launch_bounds__(NT, 8)
void temporal_compressor_kernel(const float* __restrict__ encoded,
                                const float* __restrict__ ratio,
                                float* __restrict__ out)
{
    __shared__ __align__(16) float buf[SBUF];              // 16.4 KB
    __shared__ __align__(8)  unsigned long long mbar;

    const int chunk = blockIdx.x;          // 0..NC-1
    const int d     = blockIdx.y;
    const int b     = blockIdx.z;
    const int tid   = threadIdx.x;

    // Per-batch window parameters (uniform across block)
    const float r = __ldg(&ratio[b]);
    float Lf = floorf((float)TO_ * r);     // fp32 floor, exactly like reference
    int   L  = (int)Lf;
    if (L > T_) { L = T_; Lf = (float)T_; }
    const int   start = (T_ - L) >> 1;
    const float scale = Lf * (1.0f / (float)TO_);
    const float Lm1f  = (float)(L - 1);
    const int   Lm1   = L - 1;

    const int i0 = chunk * C_;

    // Source sub-window [g0, g1] (window-relative) needed by outputs
    // [i0, i0+C_), computed with the SAME clamped expression as the interp
    // loop (x is monotonic in i, so endpoints bound everything between).
    float x0 = fmaf((float)i0 + 0.5f, scale, -0.5f);
    x0 = fminf(fmaxf(x0, 0.0f), Lm1f);
    const int g0 = (int)x0;
    float x1 = fmaf((float)(i0 + C_ - 1) + 0.5f, scale, -0.5f);
    x1 = fminf(fmaxf(x1, 0.0f), Lm1f);
    const int g1 = min((int)x1 + 1, Lm1);

    // Absolute row offset of window start; align DOWN to 16B within the row.
    const int s0        = start + g0;
    const int aligned_g = s0 & ~3;
    const int off       = s0 - aligned_g;              // 0..3
    int len = ((off + (g1 - g0 + 1) + 3) >> 2) << 2;   // round up to 4 floats
    if (aligned_g + len > T_) len = T_ - aligned_g;    // row clamp (keeps %4)

    const float* __restrict__ grow = encoded + ((size_t)b * D_ + d) * T_ + aligned_g;
    float* __restrict__ dst        = out     + ((size_t)b * D_ + d) * TO_;

    // ---- Stage sub-window into SMEM via one TMA bulk copy ----
    const uint32_t mbar_addr = (uint32_t)__cvta_generic_to_shared(&mbar);
    const uint32_t sbuf_addr = (uint32_t)__cvta_generic_to_shared(buf);
    const uint32_t bytes     = (uint32_t)len * 4u;

    if (tid == 0) {
        asm volatile("mbarrier.init.shared.b64 [%0], %1;"
                     :: "r"(mbar_addr), "r"(1) : "memory");
    }
    __syncthreads();
    if (tid == 0) {
        asm volatile("mbarrier.arrive.expect_tx.shared.b64 _, [%0], %1;"
                     :: "r"(mbar_addr), "r"(bytes) : "memory");
        asm volatile("cp.async.bulk.shared::cta.global.mbarrier::complete_tx::bytes "
                     "[%0], [%1], %2, [%3];"
                     :: "r"(sbuf_addr), "l"(grow), "r"(bytes), "r"(mbar_addr)
                     : "memory");
    }
    // All threads wait on the mbarrier (parity 0; smem is fresh every launch)
    {
        uint32_t done;
        do {
            asm volatile(
                "{\n\t.reg .pred p;\n\t"
                "mbarrier.try_wait.parity.acquire.cta.shared::cta.b64 p, [%1], %2, 0x989680;\n\t"
                "selp.b32 %0, 1, 0, p;\n\t}"
                : "=r"(done) : "r"(mbar_addr), "r"(0u) : "memory");
        } while (!done);
    }

    // buf[k] = row[aligned_g + k]  ->  window[idx] = buf[idx - g0 + off]
    const int base = off - g0;

    // ---- Interpolate from SMEM, float4 streaming stores ----
#pragma unroll
    for (int v = 0; v < V4; ++v) {
        const int i_base = i0 + (tid + v * NT) * 4;
        float res[4];
#pragma unroll
        for (int k = 0; k < 4; ++k) {
            const int i = i_base + k;
            float x = fmaf((float)i + 0.5f, scale, -0.5f);
            x = fminf(fmaxf(x, 0.0f), Lm1f);
            const int   lo = (int)x;                 // x >= 0 -> trunc == floor
            const int   hi = min(lo + 1, Lm1);
            const float w  = x - (float)lo;
            const float g_lo = buf[base + lo];
            const float g_hi = buf[base + hi];
            res[k] = fmaf(g_hi - g_lo, w, g_lo);     // g_lo*(1-w) + g_hi*w
        }
        __stcs(reinterpret_cast<float4*>(dst + i_base),
               make_float4(res[0], res[1], res[2], res[3]));
    }
}

extern "C" void kernel_launch(void* const* d_in, const int* in_sizes, int n_in,
                              void* d_out, int out_size)
{
    const float* encoded = (const float*)d_in[0];
    const float* ratio   = (const float*)d_in[1];
    float* out           = (float*)d_out;

    dim3 block(NT, 1, 1);
    dim3 grid(NC, D_, B_);   // (2, 512, 32) = 32768 blocks
    temporal_compressor_kernel<<<grid, block>>>(encoded, ratio, out);
}